// round 5
// baseline (speedup 1.0000x reference)
#include <cuda_runtime.h>

// ROI max-pool, exact replication of the JAX reference semantics:
//   ro = r>>1; amin = max(a-ro,0); amax = a+ro; if (amax > lim) amax = lim-1;
//   bin i over axis: [amin + i*L/8, amin + ceil((i+1)*L/8))   (bins may overlap by 1)
//   out[n,c,py,px] = max over (row-bin py) x (col-bin px) of feature_map[c,:,:]
//
// Layout: one block per (ROI n, 32-channel group). 256 threads = 8 warps.
// Each warp owns 4 channels and is fully independent (only __syncwarp).
// Per window row h:
//   - cooperative float4 loads of the sector-aligned window span into smem
//   - lane (cl, px) reduces its x-bin from smem, updates 8 reg accumulators
//     for whichever y-bins contain h (unrolled predicated compares).

#define HH 64
#define WW 64
#define CB 32      // channels per block
#define PITCH 52   // floats per channel row buffer (13 float4; 52%32=20 -> bank spread)

__global__ __launch_bounds__(256)
void roi_pool_kernel(const float* __restrict__ fm,
                     const int* __restrict__ rois,
                     float* __restrict__ out,
                     int Cn) {
    __shared__ float buf[8 * 4 * PITCH];   // [warp][chan-in-warp][PITCH]

    const int tid  = threadIdx.x;
    const int wid  = tid >> 5;
    const int lane = tid & 31;
    const int cl   = lane >> 3;   // channel within warp (0..3)
    const int sub  = lane & 7;    // x-lane for loads / px for reduce
    const int n    = blockIdx.y;
    const int c    = blockIdx.x * CB + wid * 4 + cl;

    const int4 r = ((const int4*)rois)[n];   // y, x, rH, rW
    const int roy = r.z >> 1;
    const int rox = r.w >> 1;
    int ymin = r.x - roy; if (ymin < 0) ymin = 0;
    int ymax = r.x + roy; if (ymax > HH) ymax = HH - 1;
    int xmin = r.y - rox; if (xmin < 0) xmin = 0;
    int xmax = r.y + rox; if (xmax > WW) xmax = WW - 1;
    const int Ly = ymax - ymin;
    const int Lx = xmax - xmin;

    // x-bin for px = sub
    const int xs = xmin + ((sub * Lx) >> 3);
    const int xe = xmin + (((sub + 1) * Lx + 7) >> 3);

    // y-bin tables (kept in registers via full unroll)
    int ys[8], ye[8];
#pragma unroll
    for (int p = 0; p < 8; p++) {
        ys[p] = ymin + ((p * Ly) >> 3);
        ye[p] = ymin + (((p + 1) * Ly + 7) >> 3);
    }

    const float NEG_INF = __int_as_float(0xff800000);
    float acc[8];
#pragma unroll
    for (int p = 0; p < 8; p++) acc[p] = NEG_INF;

    const int xlo = xmin & ~7;                       // 32B-sector aligned start
    float* wbuf = buf + (wid * 4 + cl) * PITCH;      // this channel's row buffer
    const float* fbase = fm + (size_t)c * (HH * WW) + xlo;

    for (int h = ymin; h < ymax; ++h) {
        // --- load phase: float4 chunks, lanes stride by 8 chunks ---
        const float4* src = (const float4*)(fbase + h * WW);
        float4* dst = (float4*)wbuf;
#pragma unroll 2
        for (int k = sub; xlo + 4 * k < xmax; k += 8) {
            dst[k] = src[k];
        }
        __syncwarp();

        // --- reduce phase: col-bin max for px = sub ---
        float m = NEG_INF;
        for (int x = xs; x < xe; ++x) {
            m = fmaxf(m, wbuf[x - xlo]);
        }

        // --- update whichever y-bins contain h (bins may overlap / repeat) ---
#pragma unroll
        for (int p = 0; p < 8; p++) {
            if (h >= ys[p] && h < ye[p]) acc[p] = fmaxf(acc[p], m);
        }
        __syncwarp();   // protect buf before next row's stores
    }

    // --- epilogue: out[((n*C + c)*8 + py)*8 + px] ---
    float* o = out + ((size_t)n * Cn + c) * 64 + sub;
#pragma unroll
    for (int p = 0; p < 8; p++) {
        o[p * 8] = acc[p];
    }
}

extern "C" void kernel_launch(void* const* d_in, const int* in_sizes, int n_in,
                              void* d_out, int out_size) {
    const float* fm   = (const float*)d_in[0];
    const int*   rois = (const int*)d_in[1];
    float*       out  = (float*)d_out;

    const int N = in_sizes[1] / 4;            // 512 ROIs
    const int C = in_sizes[0] / (HH * WW);    // 256 channels

    dim3 grid(C / CB, N);
    roi_pool_kernel<<<grid, 256>>>(fm, rois, out, C);
}

// round 17
// speedup vs baseline: 1.1737x; 1.1737x over previous
#include <cuda_runtime.h>

// ROI max-pool, restructured for issue-bound regime (R5 ncu: issue=82%, alu=53%,
// mem all low). Reorder reduction: vertical (rows of each y-bin) first, then
// horizontal (x-bins) — removes the per-row 8-way bin-membership update and all
// dynamic-bound scalar LDS loops.
//
// 1 warp = 1 (roi n, channel c). Block = 8 warps = 8 channels. Grid (C/8, N).
// Vertical: for each y-bin p (unrolled): lane holds 2 columns (float2), per row
//   1 LDG.64 + 2 FMNMX; store per-bin column maxes to smem (STS.64).
// Horizontal: lane = (px, p-half): 2 outputs, each = max over <=6 smem cols
//   with hoisted width predicates; coalesced STG.

#define HH 64
#define WW 64

__global__ __launch_bounds__(256)
void roi_pool_kernel(const float* __restrict__ fm,
                     const int* __restrict__ rois,
                     float* __restrict__ out,
                     int Cn) {
    __shared__ float cm[8][8][48];   // [warp][y-bin][col dx], 12.3 KB

    const int tid  = threadIdx.x;
    const int wid  = tid >> 5;
    const int lane = tid & 31;
    const int n    = blockIdx.y;
    const int c    = blockIdx.x * 8 + wid;

    const int4 r  = ((const int4*)rois)[n];     // y, x, rH, rW
    const int roy = r.z >> 1;
    const int rox = r.w >> 1;
    int ymin = r.x - roy; if (ymin < 0) ymin = 0;
    int ymax = r.x + roy; if (ymax > HH) ymax = HH - 1;   // '>' only: ==64 stays
    int xmin = r.y - rox; if (xmin < 0) xmin = 0;
    int xmax = r.y + rox; if (xmax > WW) xmax = WW - 1;
    const int Ly = ymax - ymin;                 // in [2,40]
    const int Lx = xmax - xmin;                 // in [2,40]

    const int xlo  = xmin & ~7;                 // 32B-aligned span start
    const int span = xmax - xlo;                // <= 47

    const float NEG = __int_as_float(0xff800000);   // -inf

    // lane covers columns xlo+2*lane, xlo+2*lane+1
    const bool a_lo = (2 * lane)     < span;    // first col in window span
    const bool a_hi = (2 * lane + 1) < span;    // second col in window span
    // memory safety: if span odd, highest active lane's float2 reads col xmax
    // (<=63, same row, masked by a_hi). If xmax==64, span is even (xlo 8-aligned)
    // so no lane reads past col 63.

    const float* fbase = fm + (size_t)c * (HH * WW) + xlo + 2 * lane;

    // ---- vertical: per y-bin column maxes ----
#pragma unroll
    for (int p = 0; p < 8; ++p) {
        const int ys  = ymin + ((p * Ly) >> 3);
        const int cnt = (ymin + (((p + 1) * Ly + 7) >> 3)) - ys;   // 1..6 rows

        float a0 = NEG, a1 = NEG;
        const float2* rp = (const float2*)(fbase + ys * WW);
        for (int j = 0; j < cnt; ++j) {                  // warp-uniform trips
            if (a_lo) {
                float2 v = *rp;
                a0 = fmaxf(a0, v.x);
                if (a_hi) a1 = fmaxf(a1, v.y);
            }
            rp += WW / 2;
        }
        if (a_lo) {
            cm[wid][p][2 * lane]     = a0;
            cm[wid][p][2 * lane + 1] = a1;
        }
    }
    __syncwarp();

    // ---- horizontal: lane -> (px = lane&7, p = lane>>3 and +4) ----
    const int px    = lane & 7;
    const int xs_dx = (xmin - xlo) + ((px * Lx) >> 3);
    const int width = ((xmin - xlo) + (((px + 1) * Lx + 7) >> 3)) - xs_dx; // 1..6
    const bool w1 = width > 1, w2 = width > 2, w3 = width > 3,
               w4 = width > 4, w5 = width > 5;

    const int p0 = lane >> 3;
    float* o = out + ((size_t)n * Cn + c) * 64;

    {
        const float* s = &cm[wid][p0][xs_dx];
        float m = s[0];
        if (w1) m = fmaxf(m, s[1]);
        if (w2) m = fmaxf(m, s[2]);
        if (w3) m = fmaxf(m, s[3]);
        if (w4) m = fmaxf(m, s[4]);
        if (w5) m = fmaxf(m, s[5]);
        o[lane] = m;                       // (p0*8 + px) == lane
    }
    {
        const float* s = &cm[wid][p0 + 4][xs_dx];
        float m = s[0];
        if (w1) m = fmaxf(m, s[1]);
        if (w2) m = fmaxf(m, s[2]);
        if (w3) m = fmaxf(m, s[3]);
        if (w4) m = fmaxf(m, s[4]);
        if (w5) m = fmaxf(m, s[5]);
        o[lane + 32] = m;                  // ((p0+4)*8 + px) == lane + 32
    }
}

extern "C" void kernel_launch(void* const* d_in, const int* in_sizes, int n_in,
                              void* d_out, int out_size) {
    const float* fm   = (const float*)d_in[0];
    const int*   rois = (const int*)d_in[1];
    float*       out  = (float*)d_out;

    const int N = in_sizes[1] / 4;            // 512 ROIs
    const int C = in_sizes[0] / (HH * WW);    // 256 channels

    dim3 grid(C / 8, N);
    roi_pool_kernel<<<grid, 256>>>(fm, rois, out, C);
}